// round 10
// baseline (speedup 1.0000x reference)
#include <cuda_runtime.h>
#include <cuda_bf16.h>
#include <cstdint>

#define NEXP 64
#define KDIM 1024
#define NROWS 131072
#define HIGH_NEG -100000.0f
#define CRANK0 98303u

// ---------------- scratch ----------------
#define NBINS 8192
#define CAP 8192
__device__ uint32_t g_hist1[NEXP * NBINS];
__device__ uint32_t g_cand[NEXP * CAP];
__device__ uint32_t g_cnt[NEXP];
__device__ uint32_t g_minb1[NEXP];
__device__ uint32_t g_bkt0[NEXP], g_rnk0[NEXP], g_bkt1[NEXP], g_rnk1[NEXP];
__device__ float    g_tcol[NEXP];
__device__ __nv_bfloat16 g_whi[NEXP * KDIM];
__device__ __nv_bfloat16 g_wlo[NEXP * KDIM];

// ---------------- helpers ----------------
__device__ __forceinline__ uint32_t f2o(float f) {
    uint32_t u = __float_as_uint(f);
    return u ^ ((u & 0x80000000u) ? 0xFFFFFFFFu : 0x80000000u);
}
__device__ __forceinline__ float o2f(uint32_t u) {
    u ^= ((u & 0x80000000u) ? 0x80000000u : 0xFFFFFFFFu);
    return __uint_as_float(u);
}
__device__ __forceinline__ uint32_t smem_u32(const void* p) {
    uint32_t a;
    asm("{ .reg .u64 t; cvta.to.shared.u64 t, %1; cvt.u32.u64 %0, t; }" : "=r"(a) : "l"(p));
    return a;
}
__device__ __forceinline__ void ldmx4(uint32_t* r, uint32_t addr) {
    asm volatile("ldmatrix.sync.aligned.m8n8.x4.shared.b16 {%0,%1,%2,%3}, [%4];"
                 : "=r"(r[0]), "=r"(r[1]), "=r"(r[2]), "=r"(r[3]) : "r"(addr));
}
__device__ __forceinline__ void mma_bf16(float* d, const uint32_t* a,
                                         uint32_t b0, uint32_t b1) {
    asm volatile(
        "mma.sync.aligned.m16n8k16.row.col.f32.bf16.bf16.f32 "
        "{%0,%1,%2,%3}, {%4,%5,%6,%7}, {%8,%9}, {%0,%1,%2,%3};"
        : "+f"(d[0]), "+f"(d[1]), "+f"(d[2]), "+f"(d[3])
        : "r"(a[0]), "r"(a[1]), "r"(a[2]), "r"(a[3]), "r"(b0), "r"(b1));
}
__device__ __forceinline__ void cpasync16(uint32_t dst, const void* src) {
    asm volatile("cp.async.cg.shared.global [%0], [%1], 16;"
                 :: "r"(dst), "l"(src) : "memory");
}
__device__ __forceinline__ uint32_t warp_iscan(uint32_t v, int lane) {
#pragma unroll
    for (int o = 1; o < 32; o <<= 1) {
        uint32_t t = __shfl_up_sync(0xffffffffu, v, o);
        if (lane >= o) v += t;
    }
    return v;
}

// ---------------- launch idx 0: zero hist1 ----------------
__global__ void zero_hist1() {
    uint4* a = reinterpret_cast<uint4*>(g_hist1);
    int i = blockIdx.x * blockDim.x + threadIdx.x;
    a[i] = make_uint4(0u, 0u, 0u, 0u);
}

// ---------------- launch idx 1: W -> bf16 hi/lo ----------------
__global__ void w_convert(const float* __restrict__ W) {
    int i = blockIdx.x * blockDim.x + threadIdx.x;
    float v = W[i];
    __nv_bfloat16 h = __float2bfloat16(v);
    g_whi[i] = h;
    g_wlo[i] = __float2bfloat16(v - __bfloat162float(h));
}

// ---------------- launch idx 2: small inits ----------------
__global__ void init_small() {
    if (threadIdx.x < NEXP) {
        g_cnt[threadIdx.x] = 0u;
        g_minb1[threadIdx.x] = 0xFFFFFFFFu;
    }
}

// ---------------- launch idx 3: direct-fragment mma GEMM, kk-pipelined -------
#define BM 128
#define CHUNK 64
#define NCH (KDIM / CHUNK)
#define STAGA(b) ((b) * 32768)
#define SMB(b) (65536 + (b) * 16384)
#define SMEM_TOTAL 98304
#define STG 68

__global__ __launch_bounds__(256, 2) void gemm_mma(
    const float* __restrict__ x, const float* __restrict__ bias,
    const float* __restrict__ noise, float* __restrict__ out)
{
    extern __shared__ char smem[];
    const uint32_t sb = smem_u32(smem);
    const int tid = threadIdx.x;
    const int wid = tid >> 5, lid = tid & 31;
    const int wm = wid >> 1, wn = wid & 1;     // warp grid 4 x 2
    const int rowBase = blockIdx.x * BM;
    const float* xr = x + (size_t)rowBase * KDIM;

    float acc[2][4][4];
#pragma unroll
    for (int mi = 0; mi < 2; mi++)
#pragma unroll
        for (int ni = 0; ni < 4; ni++)
#pragma unroll
            for (int j = 0; j < 4; j++) acc[mi][ni][j] = 0.0f;

    const uint32_t swA = ((uint32_t)((lid >> 2) & 3)) << 5;
    const uint32_t aCol = (uint32_t)((lid & 3) * 8);
    const uint32_t rA = (uint32_t)(wm * 32 + (lid >> 2));
    const uint32_t bmask = (uint32_t)((lid & 7) << 4);
    const uint32_t bsel = (uint32_t)(((lid >> 3) & 1) * 16);
    const uint32_t bRow0 = (uint32_t)(wn * 32 + ((lid >> 4) << 3) + (lid & 7));

    auto issue_chunk = [&](int kc, int bufsel) {
#pragma unroll
        for (int i = 0; i < 8; i++) {
            int l = tid + i * 256;
            int r = l >> 4, q = l & 15;
            uint32_t dst = sb + STAGA(bufsel) + (uint32_t)(r * 256) +
                           (((uint32_t)(q * 16)) ^ (((uint32_t)(r & 3)) << 5));
            cpasync16(dst, xr + (size_t)r * KDIM + kc + q * 4);
        }
        const char* whp = reinterpret_cast<const char*>(g_whi);
        const char* wlp = reinterpret_cast<const char*>(g_wlo);
#pragma unroll
        for (int i = 0; i < 2; i++) {
            int l = tid + i * 256;
            int e = l >> 3, q = l & 7;
            uint32_t off = (uint32_t)(e * 128) +
                           (((uint32_t)(q * 16)) ^ ((uint32_t)((e & 7) << 4)));
            size_t src = (size_t)(e * KDIM + kc) * 2 + q * 16;
            cpasync16(sb + SMB(bufsel) + off, whp + src);
            cpasync16(sb + SMB(bufsel) + 8192 + off, wlp + src);
        }
        asm volatile("cp.async.commit_group;" ::: "memory");
    };

    issue_chunk(0, 0);
    asm volatile("cp.async.wait_group 0;" ::: "memory");
    __syncthreads();

    for (int c = 0; c < NCH; c++) {
        const int buf = c & 1;
        if (c + 1 < NCH) issue_chunk((c + 1) * CHUNK, buf ^ 1);

        const uint32_t aOff = (uint32_t)STAGA(buf);
        const uint32_t bBase = sb + (uint32_t)SMB(buf);

        // raw A loader (float2 fragment loads, swizzled fp32 staging)
        auto ldA = [&](int kk, float2 (*fs)[4]) {
#pragma unroll
            for (int mi = 0; mi < 2; mi++) {
                const uint32_t R = rA + (uint32_t)(mi * 16);
                const uint32_t cb0 = ((uint32_t)(kk * 64) + aCol) ^ swA;
                const uint32_t cb1 = ((uint32_t)(kk * 64 + 32) + aCol) ^ swA;
                fs[mi][0] = *reinterpret_cast<const float2*>(smem + aOff + R * 256 + cb0);
                fs[mi][1] = *reinterpret_cast<const float2*>(smem + aOff + (R + 8) * 256 + cb0);
                fs[mi][2] = *reinterpret_cast<const float2*>(smem + aOff + R * 256 + cb1);
                fs[mi][3] = *reinterpret_cast<const float2*>(smem + aOff + (R + 8) * 256 + cb1);
            }
        };
        auto cvtA = [&](float2 (*fs)[4], uint32_t (*ah)[4], uint32_t (*al)[4]) {
#pragma unroll
            for (int mi = 0; mi < 2; mi++)
#pragma unroll
                for (int j = 0; j < 4; j++) {
                    uint32_t h;
                    asm("cvt.rn.bf16x2.f32 %0, %1, %2;" : "=r"(h)
                        : "f"(fs[mi][j].y), "f"(fs[mi][j].x));
                    float r0 = fs[mi][j].x - __uint_as_float(h << 16);
                    float r1 = fs[mi][j].y - __uint_as_float(h & 0xFFFF0000u);
                    uint32_t lo;
                    asm("cvt.rn.bf16x2.f32 %0, %1, %2;" : "=r"(lo) : "f"(r1), "f"(r0));
                    ah[mi][j] = h;
                    al[mi][j] = lo;
                }
        };
        auto ldB = [&](int kk, uint32_t* bh, uint32_t* bl) {
            const uint32_t cbB = (bsel + (uint32_t)(kk * 32)) ^ bmask;
            ldmx4(bh,     bBase + bRow0 * 128 + cbB);
            ldmx4(bh + 4, bBase + (bRow0 + 16) * 128 + cbB);
            ldmx4(bl,     bBase + 8192 + bRow0 * 128 + cbB);
            ldmx4(bl + 4, bBase + 8192 + (bRow0 + 16) * 128 + cbB);
        };

        // double-buffered fragments
        float2 fs[2][4];
        uint32_t ahb[2][2][4], alb[2][2][4], bhb[2][8], blb[2][8];

        ldA(0, fs);
        ldB(0, bhb[0], blb[0]);
        cvtA(fs, ahb[0], alb[0]);

#pragma unroll
        for (int kk = 0; kk < 4; kk++) {
            const int cur = kk & 1, nxt = cur ^ 1;
            // prefetch raw data for kk+1 (independent of this kk's MMAs)
            if (kk < 3) {
                ldA(kk + 1, fs);
                ldB(kk + 1, bhb[nxt], blb[nxt]);
            }
            // MMAs for kk: pass-major, per-acc order hh, hl, lh (bit-exact order)
#pragma unroll
            for (int mi = 0; mi < 2; mi++)
#pragma unroll
                for (int ni = 0; ni < 4; ni++) {
                    int g = (ni >> 1) * 4 + (ni & 1) * 2;
                    mma_bf16(acc[mi][ni], ahb[cur][mi], bhb[cur][g], bhb[cur][g + 1]);
                }
#pragma unroll
            for (int mi = 0; mi < 2; mi++)
#pragma unroll
                for (int ni = 0; ni < 4; ni++) {
                    int g = (ni >> 1) * 4 + (ni & 1) * 2;
                    mma_bf16(acc[mi][ni], ahb[cur][mi], blb[cur][g], blb[cur][g + 1]);
                }
#pragma unroll
            for (int mi = 0; mi < 2; mi++)
#pragma unroll
                for (int ni = 0; ni < 4; ni++) {
                    int g = (ni >> 1) * 4 + (ni & 1) * 2;
                    mma_bf16(acc[mi][ni], alb[cur][mi], bhb[cur][g], bhb[cur][g + 1]);
                }
            // convert prefetched raw A (fma pipe; overlaps tensor pipe)
            if (kk < 3) cvtA(fs, ahb[nxt], alb[nxt]);
        }

        if (c + 1 < NCH) asm volatile("cp.async.wait_group 0;" ::: "memory");
        __syncthreads();
    }

    // ---- epilogue: stage accs, coalesced write + fused hist1 ----
    float* stg = reinterpret_cast<float*>(smem);
#pragma unroll
    for (int mi = 0; mi < 2; mi++) {
        int row = wm * 32 + mi * 16 + (lid >> 2);
#pragma unroll
        for (int ni = 0; ni < 4; ni++) {
            int col = wn * 32 + ni * 8 + 2 * (lid & 3);
            *reinterpret_cast<float2*>(&stg[row * STG + col]) =
                make_float2(acc[mi][ni][0], acc[mi][ni][1]);
            *reinterpret_cast<float2*>(&stg[(row + 8) * STG + col]) =
                make_float2(acc[mi][ni][2], acc[mi][ni][3]);
        }
    }
    __syncthreads();

    const float* nz = noise + (size_t)rowBase * NEXP;
    float* op = out + (size_t)rowBase * NEXP;
#pragma unroll
    for (int j = 0; j < 8; j++) {
        int l = tid + j * 256;
        int r = l >> 4, q = (l & 15) * 4;
        float4 nv = *reinterpret_cast<const float4*>(nz + r * NEXP + q);
        float4 bv = *reinterpret_cast<const float4*>(bias + q);
        float4 o;
        o.x = (stg[r * STG + q + 0] + bv.x) + 0.1f * nv.x;
        o.y = (stg[r * STG + q + 1] + bv.y) + 0.1f * nv.y;
        o.z = (stg[r * STG + q + 2] + bv.z) + 0.1f * nv.z;
        o.w = (stg[r * STG + q + 3] + bv.w) + 0.1f * nv.w;
        *reinterpret_cast<float4*>(op + r * NEXP + q) = o;
        atomicAdd(&g_hist1[((q + 0) << 13) | (f2o(o.x) >> 19)], 1u);
        atomicAdd(&g_hist1[((q + 1) << 13) | (f2o(o.y) >> 19)], 1u);
        atomicAdd(&g_hist1[((q + 2) << 13) | (f2o(o.z) >> 19)], 1u);
        atomicAdd(&g_hist1[((q + 3) << 13) | (f2o(o.w) >> 19)], 1u);
    }
}

// ---------------- launch idx 4: locate quantile buckets ----------------
__global__ void find_buckets() {
    const int e = blockIdx.x;
    const uint32_t* h = &g_hist1[e << 13];
    const int t = threadIdx.x, lane = t & 31, w = t >> 5;
    __shared__ uint32_t sh[NBINS];
    for (int i = t; i < NBINS; i += 256) sh[i] = h[i];
    __syncthreads();
    uint32_t bins[32];
    uint32_t s = 0;
#pragma unroll
    for (int j = 0; j < 32; j++) { bins[j] = sh[t * 32 + j]; s += bins[j]; }
    __shared__ uint32_t wsum[8], woff[8];
    uint32_t ps = warp_iscan(s, lane);
    if (lane == 31) wsum[w] = ps;
    __syncthreads();
    if (t == 0) {
        uint32_t r2 = 0;
        for (int i = 0; i < 8; i++) { woff[i] = r2; r2 += wsum[i]; }
    }
    __syncthreads();
    uint32_t base = woff[w] + ps - s;
    __shared__ uint32_t rbin[2], rrnk[2];
    for (int ri = 0; ri < 2; ri++) {
        uint32_t r = CRANK0 + (uint32_t)ri;
        if (base <= r && r < base + s) {
            uint32_t cum = base;
#pragma unroll
            for (int j = 0; j < 32; j++) {
                if (r < cum + bins[j]) { rbin[ri] = (uint32_t)(t * 32 + j); rrnk[ri] = r - cum; break; }
                cum += bins[j];
            }
        }
    }
    __syncthreads();
    if (t == 0) {
        g_bkt0[e] = rbin[0]; g_rnk0[e] = rrnk[0];
        g_bkt1[e] = rbin[1]; g_rnk1[e] = rrnk[1];
    }
}

// ---------------- launch idx 5: collect candidates ----------------
__global__ void collect_pass(const float4* __restrict__ lg, int n4) {
    __shared__ uint32_t b0s[NEXP], b1s[NEXP];
    if (threadIdx.x < NEXP) {
        b0s[threadIdx.x] = g_bkt0[threadIdx.x];
        b1s[threadIdx.x] = g_bkt1[threadIdx.x];
    }
    __syncthreads();
    for (int i = blockIdx.x * blockDim.x + threadIdx.x; i < n4;
         i += gridDim.x * blockDim.x) {
        float4 v = lg[i];
        int col = (i * 4) & 63;
        float vals[4] = {v.x, v.y, v.z, v.w};
#pragma unroll
        for (int j = 0; j < 4; j++) {
            uint32_t u = f2o(vals[j]);
            uint32_t hb = u >> 19;
            int c = col + j;
            if (hb == b0s[c]) {
                uint32_t pos = atomicAdd(&g_cnt[c], 1u);
                if (pos < CAP) g_cand[(c << 13) | pos] = u;
            }
            if (b1s[c] != b0s[c] && hb == b1s[c]) atomicMin(&g_minb1[c], u);
        }
    }
}

// ---------------- launch idx 6: exact order-stats from candidates ------------
__global__ void select_kernel() {
    const int e = blockIdx.x;
    const int tid = threadIdx.x, lane = tid & 31, w = tid >> 5;
    __shared__ uint32_t hist[4096];
    const uint32_t* cand = &g_cand[e << 13];
    int n = (int)g_cnt[e]; if (n > CAP) n = CAP;
    const uint32_t b0 = g_bkt0[e], b1 = g_bkt1[e];
    const int two = (b0 == b1) ? 1 : 0;
#pragma unroll
    for (int j = 0; j < 16; j++) hist[tid * 16 + j] = 0u;
    __syncthreads();
    for (int i = tid; i < n; i += 256) atomicAdd(&hist[(cand[i] >> 7) & 0xFFFu], 1u);
    __syncthreads();
    uint32_t loc[16];
    uint32_t s = 0;
#pragma unroll
    for (int j = 0; j < 16; j++) { loc[j] = hist[tid * 16 + j]; s += loc[j]; }
    __shared__ uint32_t wsum[8], woff[8];
    uint32_t ps = warp_iscan(s, lane);
    if (lane == 31) wsum[w] = ps;
    __syncthreads();
    if (tid == 0) {
        uint32_t r2 = 0;
        for (int i = 0; i < 8; i++) { woff[i] = r2; r2 += wsum[i]; }
    }
    __syncthreads();
    uint32_t base = woff[w] + ps - s;
    __shared__ uint32_t tb[2], bb[2];
    uint32_t ranks[2] = {g_rnk0[e], g_rnk1[e]};
    for (int ri = 0; ri <= two; ri++) {
        uint32_t r = ranks[ri];
        if (base <= r && r < base + s) {
            uint32_t cum = base;
#pragma unroll
            for (int j = 0; j < 16; j++) {
                if (r < cum + loc[j]) { tb[ri] = (uint32_t)(tid * 16 + j); bb[ri] = cum; break; }
                cum += loc[j];
            }
        }
    }
    __syncthreads();
    __shared__ uint32_t mbuf[2][64];
    __shared__ uint32_t mcnt[2];
    if (tid < 2) mcnt[tid] = 0u;
    __syncthreads();
    for (int i = tid; i < n; i += 256) {
        uint32_t u = cand[i];
        uint32_t bin = (u >> 7) & 0xFFFu;
        for (int ri = 0; ri <= two; ri++) {
            if (bin == tb[ri]) {
                uint32_t k = atomicAdd(&mcnt[ri], 1u);
                if (k < 64) mbuf[ri][k] = u;
            }
        }
    }
    __syncthreads();
    if (tid == 0) {
        uint32_t vals[2];
        for (int ri = 0; ri <= two; ri++) {
            int m = (int)mcnt[ri]; if (m > 64) m = 64;
            for (int i2 = 1; i2 < m; i2++) {
                uint32_t key = mbuf[ri][i2];
                int j2 = i2 - 1;
                while (j2 >= 0 && mbuf[ri][j2] > key) { mbuf[ri][j2 + 1] = mbuf[ri][j2]; j2--; }
                mbuf[ri][j2 + 1] = key;
            }
            vals[ri] = mbuf[ri][ranks[ri] - bb[ri]];
        }
        float s0 = o2f(vals[0]);
        float s1 = two ? o2f(vals[1]) : o2f(g_minb1[e]);
        g_tcol[e] = s0 + 0.25f * (s1 - s0);
    }
}

// ---------------- launch idx 7: row masks + softmax ----------------
__global__ __launch_bounds__(256) void row_kernel(float* __restrict__ lg) {
    __shared__ float tc[NEXP];
    const int tid = threadIdx.x;
    if (tid < NEXP) tc[tid] = g_tcol[tid];
    __syncthreads();
    const int lane = tid & 31;
    const int w = tid >> 5;
    const int row = blockIdx.x * 8 + w;

    float v0 = lg[row * NEXP + lane];
    float v1 = lg[row * NEXP + 32 + lane];
    float m0 = (v0 > tc[lane])      ? v0 : HIGH_NEG;
    float m1 = (v1 > tc[lane + 32]) ? v1 : HIGH_NEG;

    float a = fmaxf(m0, m1), b = fminf(m0, m1), c = -3.402823466e38f;
#pragma unroll
    for (int off = 16; off > 0; off >>= 1) {
        float a2 = __shfl_xor_sync(0xffffffffu, a, off);
        float b2 = __shfl_xor_sync(0xffffffffu, b, off);
        float c2 = __shfl_xor_sync(0xffffffffu, c, off);
        float o1, o2, o3;
        if (a >= a2) {
            o1 = a;
            if (b >= a2) { o2 = b;  o3 = fmaxf(c, a2); }
            else         { o2 = a2; o3 = fmaxf(b, b2); }
        } else {
            o1 = a2;
            if (b2 >= a) { o2 = b2; o3 = fmaxf(c2, a); }
            else         { o2 = a;  o3 = fmaxf(b, b2); }
        }
        a = o1; b = o2; c = o3;
    }
    float thr = c + 0.03125f * (b - c);
    float w0 = (m0 > thr) ? m0 : HIGH_NEG;
    float w1 = (m1 > thr) ? m1 : HIGH_NEG;
    float M = (a > thr) ? a : HIGH_NEG;

    float e0 = expf(w0 - M);
    float e1 = expf(w1 - M);
    float ssum = e0 + e1;
#pragma unroll
    for (int off = 16; off > 0; off >>= 1)
        ssum += __shfl_xor_sync(0xffffffffu, ssum, off);

    lg[row * NEXP + lane]      = e0 / ssum;
    lg[row * NEXP + 32 + lane] = e1 / ssum;
}

// ---------------- launch ----------------
extern "C" void kernel_launch(void* const* d_in, const int* in_sizes, int n_in,
                              void* d_out, int out_size) {
    const float *x = nullptr, *noise = nullptr, *W = nullptr, *bias = nullptr;
    for (int i = 0; i < n_in; i++) {
        switch (in_sizes[i]) {
            case NROWS * KDIM: x     = (const float*)d_in[i]; break;
            case NROWS * NEXP: noise = (const float*)d_in[i]; break;
            case NEXP * KDIM:  W     = (const float*)d_in[i]; break;
            case NEXP:         bias  = (const float*)d_in[i]; break;
            default: break;
        }
    }
    float* out = (float*)d_out;
    const int n4 = NROWS * NEXP / 4;

    cudaFuncSetAttribute(gemm_mma, cudaFuncAttributeMaxDynamicSharedMemorySize, SMEM_TOTAL);

    zero_hist1<<<NEXP * NBINS / 4 / 256, 256>>>();          // idx 0
    w_convert<<<NEXP * KDIM / 256, 256>>>(W);               // idx 1
    init_small<<<1, 64>>>();                                // idx 2
    gemm_mma<<<NROWS / BM, 256, SMEM_TOTAL>>>(x, bias, noise, out);  // idx 3 (profiled)
    find_buckets<<<NEXP, 256>>>();                          // idx 4
    collect_pass<<<4096, 256>>>((const float4*)out, n4);    // idx 5
    select_kernel<<<NEXP, 256>>>();                         // idx 6
    row_kernel<<<NROWS / 8, 256>>>(out);                    // idx 7
}

// round 13
// speedup vs baseline: 1.0059x; 1.0059x over previous
#include <cuda_runtime.h>
#include <cuda_bf16.h>
#include <cstdint>

#define NEXP 64
#define KDIM 1024
#define NROWS 131072
#define HIGH_NEG -100000.0f
#define CRANK0 98303u

// ---------------- scratch ----------------
#define NBINS 8192
#define CAP 8192
__device__ uint32_t g_hist1[NEXP * NBINS];
__device__ uint32_t g_cand[NEXP * CAP];
__device__ uint32_t g_cnt[NEXP];
__device__ uint32_t g_minb1[NEXP];
__device__ uint32_t g_bkt0[NEXP], g_rnk0[NEXP], g_bkt1[NEXP], g_rnk1[NEXP];
__device__ float    g_tcol[NEXP];
__device__ __nv_bfloat16 g_whi[NEXP * KDIM];
__device__ __nv_bfloat16 g_wlo[NEXP * KDIM];
__device__ uint32_t g_done_fb;
__device__ uint32_t g_done_sel;

// ---------------- helpers ----------------
__device__ __forceinline__ uint32_t f2o(float f) {
    uint32_t u = __float_as_uint(f);
    return u ^ ((u & 0x80000000u) ? 0xFFFFFFFFu : 0x80000000u);
}
__device__ __forceinline__ float o2f(uint32_t u) {
    u ^= ((u & 0x80000000u) ? 0x80000000u : 0xFFFFFFFFu);
    return __uint_as_float(u);
}
__device__ __forceinline__ uint32_t smem_u32(const void* p) {
    uint32_t a;
    asm("{ .reg .u64 t; cvta.to.shared.u64 t, %1; cvt.u32.u64 %0, t; }" : "=r"(a) : "l"(p));
    return a;
}
__device__ __forceinline__ void ldmx4(uint32_t* r, uint32_t addr) {
    asm volatile("ldmatrix.sync.aligned.m8n8.x4.shared.b16 {%0,%1,%2,%3}, [%4];"
                 : "=r"(r[0]), "=r"(r[1]), "=r"(r[2]), "=r"(r[3]) : "r"(addr));
}
__device__ __forceinline__ void mma_bf16(float* d, const uint32_t* a,
                                         uint32_t b0, uint32_t b1) {
    asm volatile(
        "mma.sync.aligned.m16n8k16.row.col.f32.bf16.bf16.f32 "
        "{%0,%1,%2,%3}, {%4,%5,%6,%7}, {%8,%9}, {%0,%1,%2,%3};"
        : "+f"(d[0]), "+f"(d[1]), "+f"(d[2]), "+f"(d[3])
        : "r"(a[0]), "r"(a[1]), "r"(a[2]), "r"(a[3]), "r"(b0), "r"(b1));
}
__device__ __forceinline__ void cpasync16(uint32_t dst, const void* src) {
    asm volatile("cp.async.cg.shared.global [%0], [%1], 16;"
                 :: "r"(dst), "l"(src) : "memory");
}
__device__ __forceinline__ uint32_t warp_iscan(uint32_t v, int lane) {
#pragma unroll
    for (int o = 1; o < 32; o <<= 1) {
        uint32_t t = __shfl_up_sync(0xffffffffu, v, o);
        if (lane >= o) v += t;
    }
    return v;
}
__device__ __forceinline__ void spin_until(uint32_t* flag, uint32_t target) {
    uint32_t d;
    while (true) {
        asm volatile("ld.global.acquire.gpu.u32 %0, [%1];" : "=r"(d) : "l"(flag));
        if (d >= target) break;
        __nanosleep(64);
    }
}

// ---------------- launch idx 0: fused setup ----------------
__global__ void setup(const float* __restrict__ W) {
    int i = blockIdx.x * blockDim.x + threadIdx.x;   // 512*256 = 131072 threads
    // zero hist1 (NEXP*NBINS words = 131072 uint4)
    reinterpret_cast<uint4*>(g_hist1)[i] = make_uint4(0u, 0u, 0u, 0u);
    // W split (65536 elements)
    if (i < NEXP * KDIM) {
        float v = W[i];
        __nv_bfloat16 h = __float2bfloat16(v);
        g_whi[i] = h;
        g_wlo[i] = __float2bfloat16(v - __bfloat162float(h));
    }
    if (i < NEXP) {
        g_cnt[i] = 0u;
        g_minb1[i] = 0xFFFFFFFFu;
    }
    if (i == 0) { g_done_fb = 0u; g_done_sel = 0u; }
}

// ---------------- launch idx 1: direct-fragment mma GEMM (R9 exact) ----------
#define BM 128
#define CHUNK 64
#define NCH (KDIM / CHUNK)
#define STAGA(b) ((b) * 32768)
#define SMB(b) (65536 + (b) * 16384)
#define SMEM_TOTAL 98304
#define STG 68

__global__ __launch_bounds__(256, 2) void gemm_mma(
    const float* __restrict__ x, const float* __restrict__ bias,
    const float* __restrict__ noise, float* __restrict__ out)
{
    extern __shared__ char smem[];
    const uint32_t sb = smem_u32(smem);
    const int tid = threadIdx.x;
    const int wid = tid >> 5, lid = tid & 31;
    const int wm = wid >> 1, wn = wid & 1;     // warp grid 4 x 2
    const int rowBase = blockIdx.x * BM;
    const float* xr = x + (size_t)rowBase * KDIM;

    float acc[2][4][4];
#pragma unroll
    for (int mi = 0; mi < 2; mi++)
#pragma unroll
        for (int ni = 0; ni < 4; ni++)
#pragma unroll
            for (int j = 0; j < 4; j++) acc[mi][ni][j] = 0.0f;

    const uint32_t swA = ((uint32_t)((lid >> 2) & 3)) << 5;
    const uint32_t aCol = (uint32_t)((lid & 3) * 8);
    const uint32_t rA = (uint32_t)(wm * 32 + (lid >> 2));
    const uint32_t bmask = (uint32_t)((lid & 7) << 4);
    const uint32_t bsel = (uint32_t)(((lid >> 3) & 1) * 16);
    const uint32_t bRow0 = (uint32_t)(wn * 32 + ((lid >> 4) << 3) + (lid & 7));

    auto issue_chunk = [&](int kc, int bufsel) {
#pragma unroll
        for (int i = 0; i < 8; i++) {
            int l = tid + i * 256;
            int r = l >> 4, q = l & 15;
            uint32_t dst = sb + STAGA(bufsel) + (uint32_t)(r * 256) +
                           (((uint32_t)(q * 16)) ^ (((uint32_t)(r & 3)) << 5));
            cpasync16(dst, xr + (size_t)r * KDIM + kc + q * 4);
        }
        const char* whp = reinterpret_cast<const char*>(g_whi);
        const char* wlp = reinterpret_cast<const char*>(g_wlo);
#pragma unroll
        for (int i = 0; i < 2; i++) {
            int l = tid + i * 256;
            int e = l >> 3, q = l & 7;
            uint32_t off = (uint32_t)(e * 128) +
                           (((uint32_t)(q * 16)) ^ ((uint32_t)((e & 7) << 4)));
            size_t src = (size_t)(e * KDIM + kc) * 2 + q * 16;
            cpasync16(sb + SMB(bufsel) + off, whp + src);
            cpasync16(sb + SMB(bufsel) + 8192 + off, wlp + src);
        }
        asm volatile("cp.async.commit_group;" ::: "memory");
    };

    issue_chunk(0, 0);
    asm volatile("cp.async.wait_group 0;" ::: "memory");
    __syncthreads();

    for (int c = 0; c < NCH; c++) {
        const int buf = c & 1;
        if (c + 1 < NCH) issue_chunk((c + 1) * CHUNK, buf ^ 1);

        const uint32_t aOff = (uint32_t)STAGA(buf);
        const uint32_t bBase = sb + (uint32_t)SMB(buf);
#pragma unroll
        for (int kk = 0; kk < 4; kk++) {
            uint32_t ah[2][4], al[2][4];
#pragma unroll
            for (int mi = 0; mi < 2; mi++) {
                const uint32_t R = rA + (uint32_t)(mi * 16);
                const uint32_t cb0 = ((uint32_t)(kk * 64) + aCol) ^ swA;
                const uint32_t cb1 = ((uint32_t)(kk * 64 + 32) + aCol) ^ swA;
                float2 f0 = *reinterpret_cast<const float2*>(smem + aOff + R * 256 + cb0);
                float2 f1 = *reinterpret_cast<const float2*>(smem + aOff + (R + 8) * 256 + cb0);
                float2 f2 = *reinterpret_cast<const float2*>(smem + aOff + R * 256 + cb1);
                float2 f3 = *reinterpret_cast<const float2*>(smem + aOff + (R + 8) * 256 + cb1);
                float2 fs[4] = {f0, f1, f2, f3};
#pragma unroll
                for (int j = 0; j < 4; j++) {
                    uint32_t h;
                    asm("cvt.rn.bf16x2.f32 %0, %1, %2;" : "=r"(h) : "f"(fs[j].y), "f"(fs[j].x));
                    float r0 = fs[j].x - __uint_as_float(h << 16);
                    float r1 = fs[j].y - __uint_as_float(h & 0xFFFF0000u);
                    uint32_t lo;
                    asm("cvt.rn.bf16x2.f32 %0, %1, %2;" : "=r"(lo) : "f"(r1), "f"(r0));
                    ah[mi][j] = h;
                    al[mi][j] = lo;
                }
            }
            uint32_t bh[8], bl[8];
            const uint32_t cbB = (bsel + (uint32_t)(kk * 32)) ^ bmask;
            ldmx4(bh,     bBase + bRow0 * 128 + cbB);
            ldmx4(bh + 4, bBase + (bRow0 + 16) * 128 + cbB);
            ldmx4(bl,     bBase + 8192 + bRow0 * 128 + cbB);
            ldmx4(bl + 4, bBase + 8192 + (bRow0 + 16) * 128 + cbB);

#pragma unroll
            for (int mi = 0; mi < 2; mi++)
#pragma unroll
                for (int ni = 0; ni < 4; ni++) {
                    int g = (ni >> 1) * 4 + (ni & 1) * 2;
                    mma_bf16(acc[mi][ni], ah[mi], bh[g], bh[g + 1]);
                }
#pragma unroll
            for (int mi = 0; mi < 2; mi++)
#pragma unroll
                for (int ni = 0; ni < 4; ni++) {
                    int g = (ni >> 1) * 4 + (ni & 1) * 2;
                    mma_bf16(acc[mi][ni], ah[mi], bl[g], bl[g + 1]);
                }
#pragma unroll
            for (int mi = 0; mi < 2; mi++)
#pragma unroll
                for (int ni = 0; ni < 4; ni++) {
                    int g = (ni >> 1) * 4 + (ni & 1) * 2;
                    mma_bf16(acc[mi][ni], al[mi], bh[g], bh[g + 1]);
                }
        }
        if (c + 1 < NCH) asm volatile("cp.async.wait_group 0;" ::: "memory");
        __syncthreads();
    }

    // epilogue: stage accs, coalesced write + fused 13-bit hist1
    float* stg = reinterpret_cast<float*>(smem);
#pragma unroll
    for (int mi = 0; mi < 2; mi++) {
        int row = wm * 32 + mi * 16 + (lid >> 2);
#pragma unroll
        for (int ni = 0; ni < 4; ni++) {
            int col = wn * 32 + ni * 8 + 2 * (lid & 3);
            *reinterpret_cast<float2*>(&stg[row * STG + col]) =
                make_float2(acc[mi][ni][0], acc[mi][ni][1]);
            *reinterpret_cast<float2*>(&stg[(row + 8) * STG + col]) =
                make_float2(acc[mi][ni][2], acc[mi][ni][3]);
        }
    }
    __syncthreads();

    const float* nz = noise + (size_t)rowBase * NEXP;
    float* op = out + (size_t)rowBase * NEXP;
#pragma unroll
    for (int j = 0; j < 8; j++) {
        int l = tid + j * 256;
        int r = l >> 4, q = (l & 15) * 4;
        float4 nv = *reinterpret_cast<const float4*>(nz + r * NEXP + q);
        float4 bv = *reinterpret_cast<const float4*>(bias + q);
        float4 o;
        o.x = (stg[r * STG + q + 0] + bv.x) + 0.1f * nv.x;
        o.y = (stg[r * STG + q + 1] + bv.y) + 0.1f * nv.y;
        o.z = (stg[r * STG + q + 2] + bv.z) + 0.1f * nv.z;
        o.w = (stg[r * STG + q + 3] + bv.w) + 0.1f * nv.w;
        *reinterpret_cast<float4*>(op + r * NEXP + q) = o;
        atomicAdd(&g_hist1[((q + 0) << 13) | (f2o(o.x) >> 19)], 1u);
        atomicAdd(&g_hist1[((q + 1) << 13) | (f2o(o.y) >> 19)], 1u);
        atomicAdd(&g_hist1[((q + 2) << 13) | (f2o(o.z) >> 19)], 1u);
        atomicAdd(&g_hist1[((q + 3) << 13) | (f2o(o.w) >> 19)], 1u);
    }
}

// ---------------- launch idx 2: fused find_buckets + collect -----------------
__global__ __launch_bounds__(256) void fb_collect(const float4* __restrict__ lg, int n4) {
    __shared__ uint32_t sh[NBINS];          // 32 KB (fb stage)
    __shared__ uint32_t wsum[8], woff[8];
    __shared__ uint32_t rbin[2], rrnk[2];
    __shared__ uint32_t b0s[NEXP], b1s[NEXP];
    const int tid = threadIdx.x, lane = tid & 31, w = tid >> 5;

    if (blockIdx.x < NEXP) {
        // ---- find_buckets for expert e ----
        const int e = blockIdx.x;
        const uint32_t* h = &g_hist1[e << 13];
        for (int i = tid; i < NBINS; i += 256) sh[i] = h[i];
        __syncthreads();
        uint32_t bins[32];
        uint32_t s = 0;
#pragma unroll
        for (int j = 0; j < 32; j++) { bins[j] = sh[tid * 32 + j]; s += bins[j]; }
        uint32_t ps = warp_iscan(s, lane);
        if (lane == 31) wsum[w] = ps;
        __syncthreads();
        if (tid == 0) {
            uint32_t r2 = 0;
            for (int i = 0; i < 8; i++) { woff[i] = r2; r2 += wsum[i]; }
        }
        __syncthreads();
        uint32_t base = woff[w] + ps - s;
        for (int ri = 0; ri < 2; ri++) {
            uint32_t r = CRANK0 + (uint32_t)ri;
            if (base <= r && r < base + s) {
                uint32_t cum = base;
#pragma unroll
                for (int j = 0; j < 32; j++) {
                    if (r < cum + bins[j]) { rbin[ri] = (uint32_t)(tid * 32 + j); rrnk[ri] = r - cum; break; }
                    cum += bins[j];
                }
            }
        }
        __syncthreads();
        if (tid == 0) {
            g_bkt0[e] = rbin[0]; g_rnk0[e] = rrnk[0];
            g_bkt1[e] = rbin[1]; g_rnk1[e] = rrnk[1];
            __threadfence();
            atomicAdd(&g_done_fb, 1u);
        }
    }

    // ---- wait for all buckets, then collect ----
    if (tid == 0) spin_until(&g_done_fb, NEXP);
    __syncthreads();
    if (tid < NEXP) {
        b0s[tid] = g_bkt0[tid];
        b1s[tid] = g_bkt1[tid];
    }
    __syncthreads();

    for (int i = blockIdx.x * 256 + tid; i < n4; i += gridDim.x * 256) {
        float4 v = lg[i];
        int col = (i * 4) & 63;
        float vals[4] = {v.x, v.y, v.z, v.w};
#pragma unroll
        for (int j = 0; j < 4; j++) {
            uint32_t u = f2o(vals[j]);
            uint32_t hb = u >> 19;
            int c = col + j;
            if (hb == b0s[c]) {
                uint32_t pos = atomicAdd(&g_cnt[c], 1u);
                if (pos < CAP) g_cand[(c << 13) | pos] = u;
            }
            if (b1s[c] != b0s[c] && hb == b1s[c]) atomicMin(&g_minb1[c], u);
        }
    }
}

// ---------------- launch idx 3: fused select + row ---------------------------
__global__ __launch_bounds__(256) void sel_row(float* __restrict__ lg) {
    __shared__ uint32_t hist[4096];         // 16 KB (select stage)
    __shared__ uint32_t wsum[8], woff[8];
    __shared__ uint32_t tb[2], bb[2];
    __shared__ uint32_t mbuf[2][64];
    __shared__ uint32_t mcnt[2];
    __shared__ float tc[NEXP];
    const int tid = threadIdx.x, lane = tid & 31, w = tid >> 5;

    if (blockIdx.x < NEXP) {
        // ---- select for expert e ----
        const int e = blockIdx.x;
        const uint32_t* cand = &g_cand[e << 13];
        int n = (int)g_cnt[e]; if (n > CAP) n = CAP;
        const uint32_t b0 = g_bkt0[e], b1 = g_bkt1[e];
        const int two = (b0 == b1) ? 1 : 0;
#pragma unroll
        for (int j = 0; j < 16; j++) hist[tid * 16 + j] = 0u;
        __syncthreads();
        for (int i = tid; i < n; i += 256) atomicAdd(&hist[(cand[i] >> 7) & 0xFFFu], 1u);
        __syncthreads();
        uint32_t loc[16];
        uint32_t s = 0;
#pragma unroll
        for (int j = 0; j < 16; j++) { loc[j] = hist[tid * 16 + j]; s += loc[j]; }
        uint32_t ps = warp_iscan(s, lane);
        if (lane == 31) wsum[w] = ps;
        __syncthreads();
        if (tid == 0) {
            uint32_t r2 = 0;
            for (int i = 0; i < 8; i++) { woff[i] = r2; r2 += wsum[i]; }
        }
        __syncthreads();
        uint32_t base = woff[w] + ps - s;
        uint32_t ranks[2] = {g_rnk0[e], g_rnk1[e]};
        for (int ri = 0; ri <= two; ri++) {
            uint32_t r = ranks[ri];
            if (base <= r && r < base + s) {
                uint32_t cum = base;
#pragma unroll
                for (int j = 0; j < 16; j++) {
                    if (r < cum + loc[j]) { tb[ri] = (uint32_t)(tid * 16 + j); bb[ri] = cum; break; }
                    cum += loc[j];
                }
            }
        }
        __syncthreads();
        if (tid < 2) mcnt[tid] = 0u;
        __syncthreads();
        for (int i = tid; i < n; i += 256) {
            uint32_t u = cand[i];
            uint32_t bin = (u >> 7) & 0xFFFu;
            for (int ri = 0; ri <= two; ri++) {
                if (bin == tb[ri]) {
                    uint32_t k = atomicAdd(&mcnt[ri], 1u);
                    if (k < 64) mbuf[ri][k] = u;
                }
            }
        }
        __syncthreads();
        if (tid == 0) {
            uint32_t vals[2];
            for (int ri = 0; ri <= two; ri++) {
                int m = (int)mcnt[ri]; if (m > 64) m = 64;
                for (int i2 = 1; i2 < m; i2++) {
                    uint32_t key = mbuf[ri][i2];
                    int j2 = i2 - 1;
                    while (j2 >= 0 && mbuf[ri][j2] > key) { mbuf[ri][j2 + 1] = mbuf[ri][j2]; j2--; }
                    mbuf[ri][j2 + 1] = key;
                }
                vals[ri] = mbuf[ri][ranks[ri] - bb[ri]];
            }
            float s0 = o2f(vals[0]);
            float s1 = two ? o2f(vals[1]) : o2f(g_minb1[e]);
            g_tcol[e] = s0 + 0.25f * (s1 - s0);
            __threadfence();
            atomicAdd(&g_done_sel, 1u);
        }
    }

    // ---- wait for all thresholds, then row masks + softmax ----
    if (tid == 0) spin_until(&g_done_sel, NEXP);
    __syncthreads();
    if (tid < NEXP) tc[tid] = g_tcol[tid];
    __syncthreads();

    const int row = blockIdx.x * 8 + w;
    float v0 = lg[row * NEXP + lane];
    float v1 = lg[row * NEXP + 32 + lane];
    float m0 = (v0 > tc[lane])      ? v0 : HIGH_NEG;
    float m1 = (v1 > tc[lane + 32]) ? v1 : HIGH_NEG;

    float a = fmaxf(m0, m1), b = fminf(m0, m1), c = -3.402823466e38f;
#pragma unroll
    for (int off = 16; off > 0; off >>= 1) {
        float a2 = __shfl_xor_sync(0xffffffffu, a, off);
        float b2 = __shfl_xor_sync(0xffffffffu, b, off);
        float c2 = __shfl_xor_sync(0xffffffffu, c, off);
        float o1, o2, o3;
        if (a >= a2) {
            o1 = a;
            if (b >= a2) { o2 = b;  o3 = fmaxf(c, a2); }
            else         { o2 = a2; o3 = fmaxf(b, b2); }
        } else {
            o1 = a2;
            if (b2 >= a) { o2 = b2; o3 = fmaxf(c2, a); }
            else         { o2 = a;  o3 = fmaxf(b, b2); }
        }
        a = o1; b = o2; c = o3;
    }
    float thr = c + 0.03125f * (b - c);
    float w0 = (m0 > thr) ? m0 : HIGH_NEG;
    float w1 = (m1 > thr) ? m1 : HIGH_NEG;
    float M = (a > thr) ? a : HIGH_NEG;

    float e0 = expf(w0 - M);
    float e1 = expf(w1 - M);
    float ssum = e0 + e1;
#pragma unroll
    for (int off = 16; off > 0; off >>= 1)
        ssum += __shfl_xor_sync(0xffffffffu, ssum, off);

    lg[row * NEXP + lane]      = e0 / ssum;
    lg[row * NEXP + 32 + lane] = e1 / ssum;
}

// ---------------- launch ----------------
extern "C" void kernel_launch(void* const* d_in, const int* in_sizes, int n_in,
                              void* d_out, int out_size) {
    const float *x = nullptr, *noise = nullptr, *W = nullptr, *bias = nullptr;
    for (int i = 0; i < n_in; i++) {
        switch (in_sizes[i]) {
            case NROWS * KDIM: x     = (const float*)d_in[i]; break;
            case NROWS * NEXP: noise = (const float*)d_in[i]; break;
            case NEXP * KDIM:  W     = (const float*)d_in[i]; break;
            case NEXP:         bias  = (const float*)d_in[i]; break;
            default: break;
        }
    }
    float* out = (float*)d_out;
    const int n4 = NROWS * NEXP / 4;

    cudaFuncSetAttribute(gemm_mma, cudaFuncAttributeMaxDynamicSharedMemorySize, SMEM_TOTAL);

    setup<<<512, 256>>>(W);                                          // idx 0
    gemm_mma<<<NROWS / BM, 256, SMEM_TOTAL>>>(x, bias, noise, out);  // idx 1
    fb_collect<<<4096, 256>>>((const float4*)out, n4);               // idx 2
    sel_row<<<NROWS / 8, 256>>>(out);                                // idx 3
}

// round 14
// speedup vs baseline: 1.0511x; 1.0449x over previous
#include <cuda_runtime.h>
#include <cuda_bf16.h>
#include <cstdint>

#define NEXP 64
#define KDIM 1024
#define NROWS 131072
#define HIGH_NEG -100000.0f
#define CRANK0 98303u

// ---------------- scratch ----------------
#define NBINS 8192
#define CAP 8192
__device__ uint32_t g_hist1[NEXP * NBINS];
__device__ uint32_t g_cand[NEXP * CAP];
__device__ uint32_t g_cnt[NEXP];
__device__ uint32_t g_minb1[NEXP];
__device__ uint32_t g_bkt0[NEXP], g_rnk0[NEXP], g_bkt1[NEXP], g_rnk1[NEXP];
__device__ float    g_tcol[NEXP];
__device__ __nv_bfloat16 g_whi[NEXP * KDIM];
__device__ __nv_bfloat16 g_wlo[NEXP * KDIM];
__device__ uint32_t g_done_fb;
__device__ uint32_t g_done_sel;

// ---------------- helpers ----------------
__device__ __forceinline__ uint32_t f2o(float f) {
    uint32_t u = __float_as_uint(f);
    return u ^ ((u & 0x80000000u) ? 0xFFFFFFFFu : 0x80000000u);
}
__device__ __forceinline__ float o2f(uint32_t u) {
    u ^= ((u & 0x80000000u) ? 0x80000000u : 0xFFFFFFFFu);
    return __uint_as_float(u);
}
__device__ __forceinline__ uint32_t smem_u32(const void* p) {
    uint32_t a;
    asm("{ .reg .u64 t; cvta.to.shared.u64 t, %1; cvt.u32.u64 %0, t; }" : "=r"(a) : "l"(p));
    return a;
}
__device__ __forceinline__ void ldmx4(uint32_t* r, uint32_t addr) {
    asm volatile("ldmatrix.sync.aligned.m8n8.x4.shared.b16 {%0,%1,%2,%3}, [%4];"
                 : "=r"(r[0]), "=r"(r[1]), "=r"(r[2]), "=r"(r[3]) : "r"(addr));
}
__device__ __forceinline__ void mma_bf16(float* d, const uint32_t* a,
                                         uint32_t b0, uint32_t b1) {
    asm volatile(
        "mma.sync.aligned.m16n8k16.row.col.f32.bf16.bf16.f32 "
        "{%0,%1,%2,%3}, {%4,%5,%6,%7}, {%8,%9}, {%0,%1,%2,%3};"
        : "+f"(d[0]), "+f"(d[1]), "+f"(d[2]), "+f"(d[3])
        : "r"(a[0]), "r"(a[1]), "r"(a[2]), "r"(a[3]), "r"(b0), "r"(b1));
}
__device__ __forceinline__ void cpasync16(uint32_t dst, const void* src) {
    asm volatile("cp.async.cg.shared.global [%0], [%1], 16;"
                 :: "r"(dst), "l"(src) : "memory");
}
__device__ __forceinline__ uint32_t warp_iscan(uint32_t v, int lane) {
#pragma unroll
    for (int o = 1; o < 32; o <<= 1) {
        uint32_t t = __shfl_up_sync(0xffffffffu, v, o);
        if (lane >= o) v += t;
    }
    return v;
}
__device__ __forceinline__ void spin_until(uint32_t* flag, uint32_t target) {
    uint32_t d;
    while (true) {
        asm volatile("ld.global.acquire.gpu.u32 %0, [%1];" : "=r"(d) : "l"(flag));
        if (d >= target) break;
        __nanosleep(64);
    }
}
#define BAR_SYNC(id, n)   asm volatile("bar.sync %0, %1;"   :: "r"(id), "r"(n) : "memory")
#define BAR_ARRIVE(id, n) asm volatile("bar.arrive %0, %1;" :: "r"(id), "r"(n) : "memory")

// ---------------- launch idx 0: fused setup ----------------
__global__ void setup(const float* __restrict__ W) {
    int i = blockIdx.x * blockDim.x + threadIdx.x;   // 131072 threads
    reinterpret_cast<uint4*>(g_hist1)[i] = make_uint4(0u, 0u, 0u, 0u);
    if (i < NEXP * KDIM) {
        float v = W[i];
        __nv_bfloat16 h = __float2bfloat16(v);
        g_whi[i] = h;
        g_wlo[i] = __float2bfloat16(v - __bfloat162float(h));
    }
    if (i < NEXP) {
        g_cnt[i] = 0u;
        g_minb1[i] = 0xFFFFFFFFu;
    }
    if (i == 0) { g_done_fb = 0u; g_done_sel = 0u; }
}

// ---------------- launch idx 1: warp-specialized mma GEMM --------------------
// Producers (warps 4-7): LDG x -> cvt hi/lo bf16 -> STS tiles; cp.async W tiles.
// Consumers (warps 0-3): ldmatrix + MMA only (3-pass bf16 split, bit-exact order).
#define BM 128
#define CHUNK 64
#define NCH (KDIM / CHUNK)
// smem layout: A(st)=st*32768 (hi 16K | lo 16K); B(st)=65536+st*16384 (hi 8K | lo 8K)
#define SM_A(st)  ((st) * 32768)
#define SM_B(st)  (65536 + (st) * 16384)
#define SMEM_TOTAL 98304
#define STG 68
// named barrier ids
#define BAR_FULL0 1
#define BAR_FREE0 3
#define BAR_CONS  5
#define BAR_STG   6

__global__ __launch_bounds__(256, 2) void gemm_ws(
    const float* __restrict__ x, const float* __restrict__ bias,
    const float* __restrict__ noise, float* __restrict__ out)
{
    extern __shared__ char smem[];
    const uint32_t sb = smem_u32(smem);
    const int tid = threadIdx.x;
    const int wid = tid >> 5, lid = tid & 31;
    const int rowBase = blockIdx.x * BM;
    const float* xr = x + (size_t)rowBase * KDIM;

    if (wid >= 4) {
        // ================= PRODUCERS =================
        const int pt = tid - 128;   // 0..127
        float4 xb[16];
        auto loadX = [&](int kc) {
#pragma unroll
            for (int i = 0; i < 16; i++) {
                int l = pt + i * 128;
                int r = l >> 4, q = l & 15;
                xb[i] = *reinterpret_cast<const float4*>(xr + (size_t)r * KDIM + kc + q * 4);
            }
        };
        auto storeA = [&](int st) {
#pragma unroll
            for (int i = 0; i < 16; i++) {
                int l = pt + i * 128;
                int r = l >> 4, q = l & 15;
                float4 v = xb[i];
                uint32_t h01, h23, l01, l23;
                asm("cvt.rn.bf16x2.f32 %0, %1, %2;" : "=r"(h01) : "f"(v.y), "f"(v.x));
                asm("cvt.rn.bf16x2.f32 %0, %1, %2;" : "=r"(h23) : "f"(v.w), "f"(v.z));
                float r0 = v.x - __uint_as_float(h01 << 16);
                float r1 = v.y - __uint_as_float(h01 & 0xFFFF0000u);
                float r2 = v.z - __uint_as_float(h23 << 16);
                float r3 = v.w - __uint_as_float(h23 & 0xFFFF0000u);
                asm("cvt.rn.bf16x2.f32 %0, %1, %2;" : "=r"(l01) : "f"(r1), "f"(r0));
                asm("cvt.rn.bf16x2.f32 %0, %1, %2;" : "=r"(l23) : "f"(r3), "f"(r2));
                uint32_t off = (uint32_t)(r * 128) +
                               (((uint32_t)(q * 8)) ^ ((uint32_t)((r & 7) << 4)));
                *reinterpret_cast<uint2*>(smem + SM_A(st) + off) = make_uint2(h01, h23);
                *reinterpret_cast<uint2*>(smem + SM_A(st) + 16384 + off) = make_uint2(l01, l23);
            }
        };
        auto issueB = [&](int kc, int st) {
            const char* whp = reinterpret_cast<const char*>(g_whi);
            const char* wlp = reinterpret_cast<const char*>(g_wlo);
#pragma unroll
            for (int i = 0; i < 4; i++) {
                int l = pt + i * 128;
                int e = l >> 3, q = l & 7;
                uint32_t off = (uint32_t)(e * 128) +
                               (((uint32_t)(q * 16)) ^ ((uint32_t)((e & 7) << 4)));
                size_t src = (size_t)(e * KDIM + kc) * 2 + q * 16;
                cpasync16(sb + SM_B(st) + off, whp + src);
                cpasync16(sb + SM_B(st) + 8192 + off, wlp + src);
            }
            asm volatile("cp.async.commit_group;" ::: "memory");
        };

        loadX(0);
        for (int c = 0; c < NCH; c++) {
            const int st = c & 1;
            if (c >= 2) BAR_SYNC(BAR_FREE0 + st, 256);
            issueB(c * CHUNK, st);
            storeA(st);
            if (c + 1 < NCH) loadX((c + 1) * CHUNK);
            asm volatile("cp.async.wait_group 0;" ::: "memory");
            BAR_ARRIVE(BAR_FULL0 + st, 256);
        }
        BAR_SYNC(BAR_STG, 256);   // wait for consumers to stage accs
    } else {
        // ================= CONSUMERS =================
        float acc[2][2][4][4];    // [g2][mi][ni][4]
#pragma unroll
        for (int g2 = 0; g2 < 2; g2++)
#pragma unroll
            for (int mi = 0; mi < 2; mi++)
#pragma unroll
                for (int ni = 0; ni < 4; ni++)
#pragma unroll
                    for (int j = 0; j < 4; j++) acc[g2][mi][ni][j] = 0.0f;

        const uint32_t amask = (uint32_t)((lid & 7) << 4);
        const uint32_t asel = (uint32_t)((lid >> 4) * 16);
        const uint32_t aRowOff = (uint32_t)(wid * 32 + (lid & 15)) * 128;
        const uint32_t bsel = (uint32_t)(((lid >> 3) & 1) * 16);
        const uint32_t bRow0 = (uint32_t)(((lid >> 4) << 3) + (lid & 7));

        for (int c = 0; c < NCH; c++) {
            const int st = c & 1;
            BAR_SYNC(BAR_FULL0 + st, 256);
            const uint32_t aHi = sb + (uint32_t)SM_A(st) + aRowOff;
            const uint32_t aLo = aHi + 16384;
            const uint32_t bHi = sb + (uint32_t)SM_B(st);
#pragma unroll
            for (int kk = 0; kk < 4; kk++) {
                const uint32_t ca = (asel + (uint32_t)(kk * 32)) ^ amask;
                const uint32_t cb = (bsel + (uint32_t)(kk * 32)) ^ amask;
                uint32_t ah[2][4], al[2][4];
#pragma unroll
                for (int mi = 0; mi < 2; mi++) {
                    ldmx4(ah[mi], aHi + (uint32_t)(mi * 2048) + ca);
                    ldmx4(al[mi], aLo + (uint32_t)(mi * 2048) + ca);
                }
#pragma unroll
                for (int g2 = 0; g2 < 2; g2++) {
                    const uint32_t bb = bHi + (uint32_t)(g2 * 32 * 128);
                    uint32_t bh[8], bl[8];
                    ldmx4(bh,     bb + bRow0 * 128 + cb);
                    ldmx4(bh + 4, bb + (bRow0 + 16) * 128 + cb);
                    ldmx4(bl,     bb + 8192 + bRow0 * 128 + cb);
                    ldmx4(bl + 4, bb + 8192 + (bRow0 + 16) * 128 + cb);
                    // pass-major; per-acc order hh, hl, lh (bit-exact)
#pragma unroll
                    for (int mi = 0; mi < 2; mi++)
#pragma unroll
                        for (int ni = 0; ni < 4; ni++)
                            mma_bf16(acc[g2][mi][ni], ah[mi], bh[ni * 2], bh[ni * 2 + 1]);
#pragma unroll
                    for (int mi = 0; mi < 2; mi++)
#pragma unroll
                        for (int ni = 0; ni < 4; ni++)
                            mma_bf16(acc[g2][mi][ni], ah[mi], bl[ni * 2], bl[ni * 2 + 1]);
#pragma unroll
                    for (int mi = 0; mi < 2; mi++)
#pragma unroll
                        for (int ni = 0; ni < 4; ni++)
                            mma_bf16(acc[g2][mi][ni], al[mi], bh[ni * 2], bh[ni * 2 + 1]);
                }
            }
            BAR_ARRIVE(BAR_FREE0 + st, 256);
        }
        // stage accs (consumers only barrier, then write, then release producers)
        BAR_SYNC(BAR_CONS, 128);
        float* stg = reinterpret_cast<float*>(smem);
#pragma unroll
        for (int g2 = 0; g2 < 2; g2++)
#pragma unroll
            for (int mi = 0; mi < 2; mi++) {
                int row = wid * 32 + mi * 16 + (lid >> 2);
#pragma unroll
                for (int ni = 0; ni < 4; ni++) {
                    int col = g2 * 32 + ni * 8 + 2 * (lid & 3);
                    *reinterpret_cast<float2*>(&stg[row * STG + col]) =
                        make_float2(acc[g2][mi][ni][0], acc[g2][mi][ni][1]);
                    *reinterpret_cast<float2*>(&stg[(row + 8) * STG + col]) =
                        make_float2(acc[g2][mi][ni][2], acc[g2][mi][ni][3]);
                }
            }
        BAR_SYNC(BAR_STG, 256);
    }

    // ---- all 256 threads: coalesced write + fused 13-bit hist1 ----
    float* stg = reinterpret_cast<float*>(smem);
    const float* nz = noise + (size_t)rowBase * NEXP;
    float* op = out + (size_t)rowBase * NEXP;
#pragma unroll
    for (int j = 0; j < 8; j++) {
        int l = tid + j * 256;
        int r = l >> 4, q = (l & 15) * 4;
        float4 nv = *reinterpret_cast<const float4*>(nz + r * NEXP + q);
        float4 bv = *reinterpret_cast<const float4*>(bias + q);
        float4 o;
        o.x = (stg[r * STG + q + 0] + bv.x) + 0.1f * nv.x;
        o.y = (stg[r * STG + q + 1] + bv.y) + 0.1f * nv.y;
        o.z = (stg[r * STG + q + 2] + bv.z) + 0.1f * nv.z;
        o.w = (stg[r * STG + q + 3] + bv.w) + 0.1f * nv.w;
        *reinterpret_cast<float4*>(op + r * NEXP + q) = o;
        atomicAdd(&g_hist1[((q + 0) << 13) | (f2o(o.x) >> 19)], 1u);
        atomicAdd(&g_hist1[((q + 1) << 13) | (f2o(o.y) >> 19)], 1u);
        atomicAdd(&g_hist1[((q + 2) << 13) | (f2o(o.z) >> 19)], 1u);
        atomicAdd(&g_hist1[((q + 3) << 13) | (f2o(o.w) >> 19)], 1u);
    }
}

// ---------------- launch idx 2: fused find_buckets + collect -----------------
__global__ __launch_bounds__(256) void fb_collect(const float4* __restrict__ lg, int n4) {
    __shared__ uint32_t sh[NBINS];
    __shared__ uint32_t wsum[8], woff[8];
    __shared__ uint32_t rbin[2], rrnk[2];
    const int tid = threadIdx.x, lane = tid & 31, w = tid >> 5;

    if (blockIdx.x < NEXP) {
        const int e = blockIdx.x;
        const uint32_t* h = &g_hist1[e << 13];
        for (int i = tid; i < NBINS; i += 256) sh[i] = h[i];
        __syncthreads();
        uint32_t bins[32];
        uint32_t s = 0;
#pragma unroll
        for (int j = 0; j < 32; j++) { bins[j] = sh[tid * 32 + j]; s += bins[j]; }
        uint32_t ps = warp_iscan(s, lane);
        if (lane == 31) wsum[w] = ps;
        __syncthreads();
        if (tid == 0) {
            uint32_t r2 = 0;
            for (int i = 0; i < 8; i++) { woff[i] = r2; r2 += wsum[i]; }
        }
        __syncthreads();
        uint32_t base = woff[w] + ps - s;
        for (int ri = 0; ri < 2; ri++) {
            uint32_t r = CRANK0 + (uint32_t)ri;
            if (base <= r && r < base + s) {
                uint32_t cum = base;
#pragma unroll
                for (int j = 0; j < 32; j++) {
                    if (r < cum + bins[j]) { rbin[ri] = (uint32_t)(tid * 32 + j); rrnk[ri] = r - cum; break; }
                    cum += bins[j];
                }
            }
        }
        __syncthreads();
        if (tid == 0) {
            g_bkt0[e] = rbin[0]; g_rnk0[e] = rrnk[0];
            g_bkt1[e] = rbin[1]; g_rnk1[e] = rrnk[1];
            __threadfence();
            atomicAdd(&g_done_fb, 1u);
        }
    }

    if (tid == 0) spin_until(&g_done_fb, NEXP);
    __syncthreads();

    // register-resident buckets: fixed 4 columns per thread (stride ≡ 0 mod 64)
    const int c0 = (tid * 4) & 63;
    uint32_t b0r[4], b1r[4];
    bool bneq[4];
#pragma unroll
    for (int j = 0; j < 4; j++) {
        b0r[j] = g_bkt0[c0 + j];
        b1r[j] = g_bkt1[c0 + j];
        bneq[j] = (b1r[j] != b0r[j]);
    }

    for (int i = blockIdx.x * 256 + tid; i < n4; i += gridDim.x * 256) {
        float4 v = lg[i];
        float vals[4] = {v.x, v.y, v.z, v.w};
#pragma unroll
        for (int j = 0; j < 4; j++) {
            uint32_t u = f2o(vals[j]);
            uint32_t hb = u >> 19;
            if (hb == b0r[j]) {
                uint32_t pos = atomicAdd(&g_cnt[c0 + j], 1u);
                if (pos < CAP) g_cand[((c0 + j) << 13) | pos] = u;
            }
            if (bneq[j] && hb == b1r[j]) atomicMin(&g_minb1[c0 + j], u);
        }
    }
}

// ---------------- launch idx 3: fused select + row ---------------------------
__global__ __launch_bounds__(256) void sel_row(float* __restrict__ lg) {
    __shared__ uint32_t hist[4096];
    __shared__ uint32_t wsum[8], woff[8];
    __shared__ uint32_t tb[2], bb[2];
    __shared__ uint32_t mbuf[2][64];
    __shared__ uint32_t mcnt[2];
    __shared__ float tc[NEXP];
    const int tid = threadIdx.x, lane = tid & 31, w = tid >> 5;

    if (blockIdx.x < NEXP) {
        const int e = blockIdx.x;
        const uint32_t* cand = &g_cand[e << 13];
        int n = (int)g_cnt[e]; if (n > CAP) n = CAP;
        const uint32_t b0 = g_bkt0[e], b1 = g_bkt1[e];
        const int two = (b0 == b1) ? 1 : 0;
#pragma unroll
        for (int j = 0; j < 16; j++) hist[tid * 16 + j] = 0u;
        __syncthreads();
        for (int i = tid; i < n; i += 256) atomicAdd(&hist[(cand[i] >> 7) & 0xFFFu], 1u);
        __syncthreads();
        uint32_t loc[16];
        uint32_t s = 0;
#pragma unroll
        for (int j = 0; j < 16; j++) { loc[j] = hist[tid * 16 + j]; s += loc[j]; }
        uint32_t ps = warp_iscan(s, lane);
        if (lane == 31) wsum[w] = ps;
        __syncthreads();
        if (tid == 0) {
            uint32_t r2 = 0;
            for (int i = 0; i < 8; i++) { woff[i] = r2; r2 += wsum[i]; }
        }
        __syncthreads();
        uint32_t base = woff[w] + ps - s;
        uint32_t ranks[2] = {g_rnk0[e], g_rnk1[e]};
        for (int ri = 0; ri <= two; ri++) {
            uint32_t r = ranks[ri];
            if (base <= r && r < base + s) {
                uint32_t cum = base;
#pragma unroll
                for (int j = 0; j < 16; j++) {
                    if (r < cum + loc[j]) { tb[ri] = (uint32_t)(tid * 16 + j); bb[ri] = cum; break; }
                    cum += loc[j];
                }
            }
        }
        __syncthreads();
        if (tid < 2) mcnt[tid] = 0u;
        __syncthreads();
        for (int i = tid; i < n; i += 256) {
            uint32_t u = cand[i];
            uint32_t bin = (u >> 7) & 0xFFFu;
            for (int ri = 0; ri <= two; ri++) {
                if (bin == tb[ri]) {
                    uint32_t k = atomicAdd(&mcnt[ri], 1u);
                    if (k < 64) mbuf[ri][k] = u;
                }
            }
        }
        __syncthreads();
        if (tid == 0) {
            uint32_t vals[2];
            for (int ri = 0; ri <= two; ri++) {
                int m = (int)mcnt[ri]; if (m > 64) m = 64;
                for (int i2 = 1; i2 < m; i2++) {
                    uint32_t key = mbuf[ri][i2];
                    int j2 = i2 - 1;
                    while (j2 >= 0 && mbuf[ri][j2] > key) { mbuf[ri][j2 + 1] = mbuf[ri][j2]; j2--; }
                    mbuf[ri][j2 + 1] = key;
                }
                vals[ri] = mbuf[ri][ranks[ri] - bb[ri]];
            }
            float s0 = o2f(vals[0]);
            float s1 = two ? o2f(vals[1]) : o2f(g_minb1[e]);
            g_tcol[e] = s0 + 0.25f * (s1 - s0);
            __threadfence();
            atomicAdd(&g_done_sel, 1u);
        }
    }

    if (tid == 0) spin_until(&g_done_sel, NEXP);
    __syncthreads();
    if (tid < NEXP) tc[tid] = g_tcol[tid];
    __syncthreads();

    const int row = blockIdx.x * 8 + w;
    float v0 = lg[row * NEXP + lane];
    float v1 = lg[row * NEXP + 32 + lane];
    float m0 = (v0 > tc[lane])      ? v0 : HIGH_NEG;
    float m1 = (v1 > tc[lane + 32]) ? v1 : HIGH_NEG;

    float a = fmaxf(m0, m1), b = fminf(m0, m1), c = -3.402823466e38f;
#pragma unroll
    for (int off = 16; off > 0; off >>= 1) {
        float a2 = __shfl_xor_sync(0xffffffffu, a, off);
        float b2 = __shfl_xor_sync(0xffffffffu, b, off);
        float c2 = __shfl_xor_sync(0xffffffffu, c, off);
        float o1, o2, o3;
        if (a >= a2) {
            o1 = a;
            if (b >= a2) { o2 = b;  o3 = fmaxf(c, a2); }
            else         { o2 = a2; o3 = fmaxf(b, b2); }
        } else {
            o1 = a2;
            if (b2 >= a) { o2 = b2; o3 = fmaxf(c2, a); }
            else         { o2 = a;  o3 = fmaxf(b, b2); }
        }
        a = o1; b = o2; c = o3;
    }
    float thr = c + 0.03125f * (b - c);
    float w0 = (m0 > thr) ? m0 : HIGH_NEG;
    float w1 = (m1 > thr) ? m1 : HIGH_NEG;
    float M = (a > thr) ? a : HIGH_NEG;

    // fast softmax: ex2.approx + rcp.approx (mask logic above unchanged)
    float e0, e1;
    asm("ex2.approx.f32 %0, %1;" : "=f"(e0) : "f"((w0 - M) * 1.4426950408889634f));
    asm("ex2.approx.f32 %0, %1;" : "=f"(e1) : "f"((w1 - M) * 1.4426950408889634f));
    float ssum = e0 + e1;
#pragma unroll
    for (int off = 16; off > 0; off >>= 1)
        ssum += __shfl_xor_sync(0xffffffffu, ssum, off);
    float inv;
    asm("rcp.approx.f32 %0, %1;" : "=f"(inv) : "f"(ssum));

    lg[row * NEXP + lane]      = e0 * inv;
    lg[row * NEXP + 32 + lane] = e1 * inv;
}

// ---------------- launch ----------------
extern "C" void kernel_launch(void* const* d_in, const int* in_sizes, int n_in,
                              void* d_out, int out_size) {
    const float *x = nullptr, *noise = nullptr, *W = nullptr, *bias = nullptr;
    for (int i = 0; i < n_in; i++) {
        switch (in_sizes[i]) {
            case NROWS * KDIM: x     = (const float*)d_in[i]; break;
            case NROWS * NEXP: noise = (const float*)d_in[i]; break;
            case NEXP * KDIM:  W     = (const float*)d_in[i]; break;
            case NEXP:         bias  = (const float*)d_in[i]; break;
            default: break;
        }
    }
    float* out = (float*)d_out;
    const int n4 = NROWS * NEXP / 4;

    cudaFuncSetAttribute(gemm_ws, cudaFuncAttributeMaxDynamicSharedMemorySize, SMEM_TOTAL);

    setup<<<512, 256>>>(W);                                          // idx 0
    gemm_ws<<<NROWS / BM, 256, SMEM_TOTAL>>>(x, bias, noise, out);   // idx 1
    fb_collect<<<4096, 256>>>((const float4*)out, n4);               // idx 2
    sel_row<<<NROWS / 8, 256>>>(out);                                // idx 3
}

// round 15
// speedup vs baseline: 1.0608x; 1.0092x over previous
#include <cuda_runtime.h>
#include <cuda_bf16.h>
#include <cstdint>

#define NEXP 64
#define KDIM 1024
#define NROWS 131072
#define HIGH_NEG -100000.0f
#define CRANK0 98303u

// ---------------- scratch ----------------
#define NBINS 8192
#define CAP 8192
__device__ uint32_t g_hist1[NEXP * NBINS];
__device__ uint32_t g_cand[NEXP * CAP];
__device__ uint32_t g_cnt[NEXP];
__device__ uint32_t g_bkt0[NEXP], g_rnk0[NEXP];
__device__ float    g_blo[NEXP], g_bhi[NEXP];
__device__ float    g_tcol[NEXP];
__device__ __nv_bfloat16 g_whi[NEXP * KDIM];
__device__ __nv_bfloat16 g_wlo[NEXP * KDIM];
__device__ uint32_t g_done_fb;
__device__ uint32_t g_done_sel;

// ---------------- helpers ----------------
__device__ __forceinline__ uint32_t f2o(float f) {
    uint32_t u = __float_as_uint(f);
    return u ^ ((u & 0x80000000u) ? 0xFFFFFFFFu : 0x80000000u);
}
__device__ __forceinline__ float o2f(uint32_t u) {
    u ^= ((u & 0x80000000u) ? 0x80000000u : 0xFFFFFFFFu);
    return __uint_as_float(u);
}
__device__ __forceinline__ uint32_t smem_u32(const void* p) {
    uint32_t a;
    asm("{ .reg .u64 t; cvta.to.shared.u64 t, %1; cvt.u32.u64 %0, t; }" : "=r"(a) : "l"(p));
    return a;
}
__device__ __forceinline__ void ldmx4(uint32_t* r, uint32_t addr) {
    asm volatile("ldmatrix.sync.aligned.m8n8.x4.shared.b16 {%0,%1,%2,%3}, [%4];"
                 : "=r"(r[0]), "=r"(r[1]), "=r"(r[2]), "=r"(r[3]) : "r"(addr));
}
__device__ __forceinline__ void mma_bf16(float* d, const uint32_t* a,
                                         uint32_t b0, uint32_t b1) {
    asm volatile(
        "mma.sync.aligned.m16n8k16.row.col.f32.bf16.bf16.f32 "
        "{%0,%1,%2,%3}, {%4,%5,%6,%7}, {%8,%9}, {%0,%1,%2,%3};"
        : "+f"(d[0]), "+f"(d[1]), "+f"(d[2]), "+f"(d[3])
        : "r"(a[0]), "r"(a[1]), "r"(a[2]), "r"(a[3]), "r"(b0), "r"(b1));
}
__device__ __forceinline__ void cpasync16(uint32_t dst, const void* src) {
    asm volatile("cp.async.cg.shared.global [%0], [%1], 16;"
                 :: "r"(dst), "l"(src) : "memory");
}
__device__ __forceinline__ uint32_t warp_iscan(uint32_t v, int lane) {
#pragma unroll
    for (int o = 1; o < 32; o <<= 1) {
        uint32_t t = __shfl_up_sync(0xffffffffu, v, o);
        if (lane >= o) v += t;
    }
    return v;
}
__device__ __forceinline__ void spin_until(uint32_t* flag, uint32_t target) {
    uint32_t d;
    while (true) {
        asm volatile("ld.global.acquire.gpu.u32 %0, [%1];" : "=r"(d) : "l"(flag));
        if (d >= target) break;
        __nanosleep(64);
    }
}
#define BAR_SYNC(id, n)   asm volatile("bar.sync %0, %1;"   :: "r"(id), "r"(n) : "memory")
#define BAR_ARRIVE(id, n) asm volatile("bar.arrive %0, %1;" :: "r"(id), "r"(n) : "memory")

// ---------------- launch idx 0: fused setup ----------------
__global__ void setup(const float* __restrict__ W) {
    int i = blockIdx.x * blockDim.x + threadIdx.x;   // 131072 threads
    reinterpret_cast<uint4*>(g_hist1)[i] = make_uint4(0u, 0u, 0u, 0u);
    if (i < NEXP * KDIM) {
        float v = W[i];
        __nv_bfloat16 h = __float2bfloat16(v);
        g_whi[i] = h;
        g_wlo[i] = __float2bfloat16(v - __bfloat162float(h));
    }
    if (i < NEXP) g_cnt[i] = 0u;
    if (i == 0) { g_done_fb = 0u; g_done_sel = 0u; }
}

// ---------------- launch idx 1: warp-specialized mma GEMM (R14 exact) --------
#define BM 128
#define CHUNK 64
#define NCH (KDIM / CHUNK)
#define SM_A(st)  ((st) * 32768)
#define SM_B(st)  (65536 + (st) * 16384)
#define SMEM_TOTAL 98304
#define STG 68
#define BAR_FULL0 1
#define BAR_FREE0 3
#define BAR_CONS  5
#define BAR_STG   6

__global__ __launch_bounds__(256, 2) void gemm_ws(
    const float* __restrict__ x, const float* __restrict__ bias,
    const float* __restrict__ noise, float* __restrict__ out)
{
    extern __shared__ char smem[];
    const uint32_t sb = smem_u32(smem);
    const int tid = threadIdx.x;
    const int wid = tid >> 5, lid = tid & 31;
    const int rowBase = blockIdx.x * BM;
    const float* xr = x + (size_t)rowBase * KDIM;

    if (wid >= 4) {
        // ================= PRODUCERS =================
        const int pt = tid - 128;
        float4 xb[16];
        auto loadX = [&](int kc) {
#pragma unroll
            for (int i = 0; i < 16; i++) {
                int l = pt + i * 128;
                int r = l >> 4, q = l & 15;
                xb[i] = *reinterpret_cast<const float4*>(xr + (size_t)r * KDIM + kc + q * 4);
            }
        };
        auto storeA = [&](int st) {
#pragma unroll
            for (int i = 0; i < 16; i++) {
                int l = pt + i * 128;
                int r = l >> 4, q = l & 15;
                float4 v = xb[i];
                uint32_t h01, h23, l01, l23;
                asm("cvt.rn.bf16x2.f32 %0, %1, %2;" : "=r"(h01) : "f"(v.y), "f"(v.x));
                asm("cvt.rn.bf16x2.f32 %0, %1, %2;" : "=r"(h23) : "f"(v.w), "f"(v.z));
                float r0 = v.x - __uint_as_float(h01 << 16);
                float r1 = v.y - __uint_as_float(h01 & 0xFFFF0000u);
                float r2 = v.z - __uint_as_float(h23 << 16);
                float r3 = v.w - __uint_as_float(h23 & 0xFFFF0000u);
                asm("cvt.rn.bf16x2.f32 %0, %1, %2;" : "=r"(l01) : "f"(r1), "f"(r0));
                asm("cvt.rn.bf16x2.f32 %0, %1, %2;" : "=r"(l23) : "f"(r3), "f"(r2));
                uint32_t off = (uint32_t)(r * 128) +
                               (((uint32_t)(q * 8)) ^ ((uint32_t)((r & 7) << 4)));
                *reinterpret_cast<uint2*>(smem + SM_A(st) + off) = make_uint2(h01, h23);
                *reinterpret_cast<uint2*>(smem + SM_A(st) + 16384 + off) = make_uint2(l01, l23);
            }
        };
        auto issueB = [&](int kc, int st) {
            const char* whp = reinterpret_cast<const char*>(g_whi);
            const char* wlp = reinterpret_cast<const char*>(g_wlo);
#pragma unroll
            for (int i = 0; i < 4; i++) {
                int l = pt + i * 128;
                int e = l >> 3, q = l & 7;
                uint32_t off = (uint32_t)(e * 128) +
                               (((uint32_t)(q * 16)) ^ ((uint32_t)((e & 7) << 4)));
                size_t src = (size_t)(e * KDIM + kc) * 2 + q * 16;
                cpasync16(sb + SM_B(st) + off, whp + src);
                cpasync16(sb + SM_B(st) + 8192 + off, wlp + src);
            }
            asm volatile("cp.async.commit_group;" ::: "memory");
        };

        loadX(0);
        for (int c = 0; c < NCH; c++) {
            const int st = c & 1;
            if (c >= 2) BAR_SYNC(BAR_FREE0 + st, 256);
            issueB(c * CHUNK, st);
            storeA(st);
            if (c + 1 < NCH) loadX((c + 1) * CHUNK);
            asm volatile("cp.async.wait_group 0;" ::: "memory");
            BAR_ARRIVE(BAR_FULL0 + st, 256);
        }
        BAR_SYNC(BAR_STG, 256);
    } else {
        // ================= CONSUMERS =================
        float acc[2][2][4][4];
#pragma unroll
        for (int g2 = 0; g2 < 2; g2++)
#pragma unroll
            for (int mi = 0; mi < 2; mi++)
#pragma unroll
                for (int ni = 0; ni < 4; ni++)
#pragma unroll
                    for (int j = 0; j < 4; j++) acc[g2][mi][ni][j] = 0.0f;

        const uint32_t amask = (uint32_t)((lid & 7) << 4);
        const uint32_t asel = (uint32_t)((lid >> 4) * 16);
        const uint32_t aRowOff = (uint32_t)(wid * 32 + (lid & 15)) * 128;
        const uint32_t bsel = (uint32_t)(((lid >> 3) & 1) * 16);
        const uint32_t bRow0 = (uint32_t)(((lid >> 4) << 3) + (lid & 7));

        for (int c = 0; c < NCH; c++) {
            const int st = c & 1;
            BAR_SYNC(BAR_FULL0 + st, 256);
            const uint32_t aHi = sb + (uint32_t)SM_A(st) + aRowOff;
            const uint32_t aLo = aHi + 16384;
            const uint32_t bHi = sb + (uint32_t)SM_B(st);
#pragma unroll
            for (int kk = 0; kk < 4; kk++) {
                const uint32_t ca = (asel + (uint32_t)(kk * 32)) ^ amask;
                const uint32_t cb = (bsel + (uint32_t)(kk * 32)) ^ amask;
                uint32_t ah[2][4], al[2][4];
#pragma unroll
                for (int mi = 0; mi < 2; mi++) {
                    ldmx4(ah[mi], aHi + (uint32_t)(mi * 2048) + ca);
                    ldmx4(al[mi], aLo + (uint32_t)(mi * 2048) + ca);
                }
#pragma unroll
                for (int g2 = 0; g2 < 2; g2++) {
                    const uint32_t bb = bHi + (uint32_t)(g2 * 32 * 128);
                    uint32_t bh[8], bl[8];
                    ldmx4(bh,     bb + bRow0 * 128 + cb);
                    ldmx4(bh + 4, bb + (bRow0 + 16) * 128 + cb);
                    ldmx4(bl,     bb + 8192 + bRow0 * 128 + cb);
                    ldmx4(bl + 4, bb + 8192 + (bRow0 + 16) * 128 + cb);
#pragma unroll
                    for (int mi = 0; mi < 2; mi++)
#pragma unroll
                        for (int ni = 0; ni < 4; ni++)
                            mma_bf16(acc[g2][mi][ni], ah[mi], bh[ni * 2], bh[ni * 2 + 1]);
#pragma unroll
                    for (int mi = 0; mi < 2; mi++)
#pragma unroll
                        for (int ni = 0; ni < 4; ni++)
                            mma_bf16(acc[g2][mi][ni], ah[mi], bl[ni * 2], bl[ni * 2 + 1]);
#pragma unroll
                    for (int mi = 0; mi < 2; mi++)
#pragma unroll
                        for (int ni = 0; ni < 4; ni++)
                            mma_bf16(acc[g2][mi][ni], al[mi], bh[ni * 2], bh[ni * 2 + 1]);
                }
            }
            BAR_ARRIVE(BAR_FREE0 + st, 256);
        }
        BAR_SYNC(BAR_CONS, 128);
        float* stg = reinterpret_cast<float*>(smem);
#pragma unroll
        for (int g2 = 0; g2 < 2; g2++)
#pragma unroll
            for (int mi = 0; mi < 2; mi++) {
                int row = wid * 32 + mi * 16 + (lid >> 2);
#pragma unroll
                for (int ni = 0; ni < 4; ni++) {
                    int col = g2 * 32 + ni * 8 + 2 * (lid & 3);
                    *reinterpret_cast<float2*>(&stg[row * STG + col]) =
                        make_float2(acc[g2][mi][ni][0], acc[g2][mi][ni][1]);
                    *reinterpret_cast<float2*>(&stg[(row + 8) * STG + col]) =
                        make_float2(acc[g2][mi][ni][2], acc[g2][mi][ni][3]);
                }
            }
        BAR_SYNC(BAR_STG, 256);
    }

    // ---- all 256 threads: coalesced write + fused 13-bit hist1 ----
    float* stg = reinterpret_cast<float*>(smem);
    const float* nz = noise + (size_t)rowBase * NEXP;
    float* op = out + (size_t)rowBase * NEXP;
#pragma unroll
    for (int j = 0; j < 8; j++) {
        int l = tid + j * 256;
        int r = l >> 4, q = (l & 15) * 4;
        float4 nv = *reinterpret_cast<const float4*>(nz + r * NEXP + q);
        float4 bv = *reinterpret_cast<const float4*>(bias + q);
        float4 o;
        o.x = (stg[r * STG + q + 0] + bv.x) + 0.1f * nv.x;
        o.y = (stg[r * STG + q + 1] + bv.y) + 0.1f * nv.y;
        o.z = (stg[r * STG + q + 2] + bv.z) + 0.1f * nv.z;
        o.w = (stg[r * STG + q + 3] + bv.w) + 0.1f * nv.w;
        *reinterpret_cast<float4*>(op + r * NEXP + q) = o;
        atomicAdd(&g_hist1[((q + 0) << 13) | (f2o(o.x) >> 19)], 1u);
        atomicAdd(&g_hist1[((q + 1) << 13) | (f2o(o.y) >> 19)], 1u);
        atomicAdd(&g_hist1[((q + 2) << 13) | (f2o(o.z) >> 19)], 1u);
        atomicAdd(&g_hist1[((q + 3) << 13) | (f2o(o.w) >> 19)], 1u);
    }
}

// ---------------- launch idx 2: fused find_buckets + collect -----------------
// Single-rank (t = s0 exact-mask theorem); float-interval fast path + exact confirm.
__global__ __launch_bounds__(256) void fb_collect(const float4* __restrict__ lg, int n4) {
    __shared__ uint32_t sh[NBINS];
    __shared__ uint32_t wsum[8], woff[8];
    __shared__ uint32_t rbin, rrnk;
    const int tid = threadIdx.x, lane = tid & 31, w = tid >> 5;

    if (blockIdx.x < NEXP) {
        const int e = blockIdx.x;
        const uint32_t* h = &g_hist1[e << 13];
        for (int i = tid; i < NBINS; i += 256) sh[i] = h[i];
        __syncthreads();
        uint32_t bins[32];
        uint32_t s = 0;
#pragma unroll
        for (int j = 0; j < 32; j++) { bins[j] = sh[tid * 32 + j]; s += bins[j]; }
        uint32_t ps = warp_iscan(s, lane);
        if (lane == 31) wsum[w] = ps;
        __syncthreads();
        if (tid == 0) {
            uint32_t r2 = 0;
            for (int i = 0; i < 8; i++) { woff[i] = r2; r2 += wsum[i]; }
        }
        __syncthreads();
        uint32_t base = woff[w] + ps - s;
        if (base <= CRANK0 && CRANK0 < base + s) {
            uint32_t cum = base;
#pragma unroll
            for (int j = 0; j < 32; j++) {
                if (CRANK0 < cum + bins[j]) { rbin = (uint32_t)(tid * 32 + j); rrnk = CRANK0 - cum; break; }
                cum += bins[j];
            }
        }
        __syncthreads();
        if (tid == 0) {
            g_bkt0[e] = rbin; g_rnk0[e] = rrnk;
            g_blo[e] = o2f(rbin << 19);
            g_bhi[e] = o2f((rbin << 19) | 0x7FFFFu);
            __threadfence();
            atomicAdd(&g_done_fb, 1u);
        }
    }

    if (tid == 0) spin_until(&g_done_fb, NEXP);
    __syncthreads();

    // register-resident buckets + float interval bounds (4 fixed columns/thread)
    const int c0 = (tid * 4) & 63;
    uint32_t b0r[4];
    float lo[4], hi[4];
#pragma unroll
    for (int j = 0; j < 4; j++) {
        b0r[j] = g_bkt0[c0 + j];
        lo[j] = g_blo[c0 + j];
        hi[j] = g_bhi[c0 + j];
    }

    for (int i = blockIdx.x * 256 + tid; i < n4; i += gridDim.x * 256) {
        float4 v = lg[i];
        float vals[4] = {v.x, v.y, v.z, v.w};
#pragma unroll
        for (int j = 0; j < 4; j++) {
            float f = vals[j];
            if (f >= lo[j] && f <= hi[j]) {
                uint32_t u = f2o(f);               // exact confirm (handles +-0 straddle)
                if ((u >> 19) == b0r[j]) {
                    uint32_t pos = atomicAdd(&g_cnt[c0 + j], 1u);
                    if (pos < CAP) g_cand[((c0 + j) << 13) | pos] = u;
                }
            }
        }
    }
}

// ---------------- launch idx 3: fused select + thread-per-row masks/softmax --
__global__ __launch_bounds__(256) void sel_row(float* __restrict__ lg) {
    __shared__ uint32_t hist[4096];
    __shared__ uint32_t wsum[8], woff[8];
    __shared__ uint32_t tb, bb;
    __shared__ uint32_t mbuf[64];
    __shared__ uint32_t mcnt;
    __shared__ __align__(16) float tc[NEXP];
    const int tid = threadIdx.x, lane = tid & 31, w = tid >> 5;

    if (blockIdx.x < NEXP) {
        // ---- select rank-98303 value exactly (single rank) ----
        const int e = blockIdx.x;
        const uint32_t* cand = &g_cand[e << 13];
        int n = (int)g_cnt[e]; if (n > CAP) n = CAP;
        const uint32_t r = g_rnk0[e];
#pragma unroll
        for (int j = 0; j < 16; j++) hist[tid * 16 + j] = 0u;
        __syncthreads();
        for (int i = tid; i < n; i += 256) atomicAdd(&hist[(cand[i] >> 7) & 0xFFFu], 1u);
        __syncthreads();
        uint32_t loc[16];
        uint32_t s = 0;
#pragma unroll
        for (int j = 0; j < 16; j++) { loc[j] = hist[tid * 16 + j]; s += loc[j]; }
        uint32_t ps = warp_iscan(s, lane);
        if (lane == 31) wsum[w] = ps;
        __syncthreads();
        if (tid == 0) {
            uint32_t r2 = 0;
            for (int i = 0; i < 8; i++) { woff[i] = r2; r2 += wsum[i]; }
            mcnt = 0u;
        }
        __syncthreads();
        uint32_t base = woff[w] + ps - s;
        if (base <= r && r < base + s) {
            uint32_t cum = base;
#pragma unroll
            for (int j = 0; j < 16; j++) {
                if (r < cum + loc[j]) { tb = (uint32_t)(tid * 16 + j); bb = cum; break; }
                cum += loc[j];
            }
        }
        __syncthreads();
        for (int i = tid; i < n; i += 256) {
            uint32_t u = cand[i];
            if (((u >> 7) & 0xFFFu) == tb) {
                uint32_t k = atomicAdd(&mcnt, 1u);
                if (k < 64) mbuf[k] = u;
            }
        }
        __syncthreads();
        if (tid == 0) {
            int m = (int)mcnt; if (m > 64) m = 64;
            for (int i2 = 1; i2 < m; i2++) {
                uint32_t key = mbuf[i2];
                int j2 = i2 - 1;
                while (j2 >= 0 && mbuf[j2] > key) { mbuf[j2 + 1] = mbuf[j2]; j2--; }
                mbuf[j2 + 1] = key;
            }
            g_tcol[e] = o2f(mbuf[r - bb]);    // t = s0 (exact mask)
            __threadfence();
            atomicAdd(&g_done_sel, 1u);
        }
    }

    if (tid == 0) spin_until(&g_done_sel, NEXP);
    __syncthreads();
    if (tid < NEXP) tc[tid] = g_tcol[tid];
    __syncthreads();

    // ---- thread-per-row: capacity mask + top-3 + softmax (branchless scan) ----
    const int row = blockIdx.x * 256 + tid;
    const float4* rp = reinterpret_cast<const float4*>(lg + (size_t)row * NEXP);
    const float4* t4 = reinterpret_cast<const float4*>(tc);

    float a = HIGH_NEG, b = HIGH_NEG, c = -3.402823466e38f;
    int ia = 0, ib = 0;
#define PROC(vv, tt, col) do {                                        \
        float m = (vv > tt) ? vv : HIGH_NEG;                          \
        bool ga = m > a, gb = m > b, gc = m > c;                      \
        float nc = gb ? b : (gc ? m : c);                             \
        int  nib = ga ? ia : (gb ? (col) : ib);                       \
        float nb = ga ? a : (gb ? m : b);                             \
        int  nia = ga ? (col) : ia;                                   \
        float na = ga ? m : a;                                        \
        a = na; b = nb; c = nc; ia = nia; ib = nib;                   \
    } while (0)

#pragma unroll
    for (int j = 0; j < 16; j++) {
        float4 v = rp[j];
        float4 t = t4[j];
        PROC(v.x, t.x, j * 4 + 0);
        PROC(v.y, t.y, j * 4 + 1);
        PROC(v.z, t.z, j * 4 + 2);
        PROC(v.w, t.w, j * 4 + 3);
    }
#undef PROC

    float* op = lg + (size_t)row * NEXP;
    float4* op4 = reinterpret_cast<float4*>(op);
    if (a > c) {
        // survivors: a always; b iff b > c  (thr = c, exact)
        bool keepb = (b > c);
        float e1;
        asm("ex2.approx.f32 %0, %1;" : "=f"(e1) : "f"((b - a) * 1.4426950408889634f));
        e1 = keepb ? e1 : 0.0f;
        float inv;
        asm("rcp.approx.f32 %0, %1;" : "=f"(inv) : "f"(1.0f + e1));
        float4 z = make_float4(0.0f, 0.0f, 0.0f, 0.0f);
#pragma unroll
        for (int j = 0; j < 16; j++) op4[j] = z;
        op[ia] = inv;                      // e0 = 1 -> e0*inv = inv
        if (keepb) op[ib] = e1 * inv;
    } else {
        // zero survivors -> reference softmax over all-equal HIGH_NEG = uniform
        float4 u = make_float4(0.015625f, 0.015625f, 0.015625f, 0.015625f);
#pragma unroll
        for (int j = 0; j < 16; j++) op4[j] = u;
    }
}

// ---------------- launch ----------------
extern "C" void kernel_launch(void* const* d_in, const int* in_sizes, int n_in,
                              void* d_out, int out_size) {
    const float *x = nullptr, *noise = nullptr, *W = nullptr, *bias = nullptr;
    for (int i = 0; i < n_in; i++) {
        switch (in_sizes[i]) {
            case NROWS * KDIM: x     = (const float*)d_in[i]; break;
            case NROWS * NEXP: noise = (const float*)d_in[i]; break;
            case NEXP * KDIM:  W     = (const float*)d_in[i]; break;
            case NEXP:         bias  = (const float*)d_in[i]; break;
            default: break;
        }
    }
    float* out = (float*)d_out;
    const int n4 = NROWS * NEXP / 4;

    cudaFuncSetAttribute(gemm_ws, cudaFuncAttributeMaxDynamicSharedMemorySize, SMEM_TOTAL);

    setup<<<512, 256>>>(W);                                          // idx 0
    gemm_ws<<<NROWS / BM, 256, SMEM_TOTAL>>>(x, bias, noise, out);   // idx 1
    fb_collect<<<4096, 256>>>((const float4*)out, n4);               // idx 2
    sel_row<<<NROWS / 256, 256>>>(out);                              // idx 3
}